// round 2
// baseline (speedup 1.0000x reference)
#include <cuda_runtime.h>
#include <cstdint>
#include <math.h>

#define N_NODES 50000
#define N_EDGES 400000

typedef unsigned long long ull;

__device__ float g_agg[(size_t)N_NODES * 64];

__device__ __forceinline__ ull pack2(float x) {
    ull r; asm("mov.b64 %0, {%1, %1};" : "=l"(r) : "f"(x)); return r;
}
__device__ __forceinline__ void fma2(ull& d, ull a, ull b) {
    asm("fma.rn.f32x2 %0, %1, %2, %0;" : "+l"(d) : "l"(a), "l"(b));
}
__device__ __forceinline__ void unpack2(ull v, float& lo, float& hi) {
    asm("mov.b64 {%0, %1}, %2;" : "=f"(lo), "=f"(hi) : "l"(v));
}

// Out[64][C] = act(In[64][K] @ W[K][C] + bias); 256 threads; 4 rows x C/32 f32x2 per thread.
template<int K, int C, int INS, int OUTS, bool RELU>
__device__ __forceinline__ void gemm_layer(const float* __restrict__ W,
                                           const float* __restrict__ bias,
                                           const float* __restrict__ In,
                                           float* __restrict__ Out,
                                           float* __restrict__ Wp, int tid)
{
    constexpr int CP = C / 32;
    constexpr int NB = K / 16;
    const int r0 = (tid >> 4) * 4;
    const int cw = (tid & 15);

    ull acc[4][CP];
#pragma unroll
    for (int i = 0; i < 4; i++)
#pragma unroll
        for (int j = 0; j < CP; j++) acc[i][j] = 0ull;

    for (int idx = tid; idx < 16 * C / 4; idx += 256)
        ((float4*)Wp)[idx] = ((const float4*)W)[idx];
    __syncthreads();

    for (int p = 0; p < NB; p++) {
        const float* wc = Wp + (p & 1) * (16 * C);
        if (p + 1 < NB) {
            float* wn = Wp + ((p + 1) & 1) * (16 * C);
            const float4* srcp = (const float4*)(W + (size_t)(p + 1) * 16 * C);
            for (int idx = tid; idx < 16 * C / 4; idx += 256)
                ((float4*)wn)[idx] = srcp[idx];
        }
        const float* xb = In + r0 * INS + p * 16;
#pragma unroll
        for (int kk = 0; kk < 16; kk++) {
            ull xd0 = pack2(xb[0 * INS + kk]);
            ull xd1 = pack2(xb[1 * INS + kk]);
            ull xd2 = pack2(xb[2 * INS + kk]);
            ull xd3 = pack2(xb[3 * INS + kk]);
            const ull* wrow = (const ull*)(wc + kk * C);
#pragma unroll
            for (int j = 0; j < CP; j++) {
                ull wv = wrow[cw + 16 * j];
                fma2(acc[0][j], xd0, wv);
                fma2(acc[1][j], xd1, wv);
                fma2(acc[2][j], xd2, wv);
                fma2(acc[3][j], xd3, wv);
            }
        }
        __syncthreads();
    }

#pragma unroll
    for (int j = 0; j < CP; j++) {
        int c = 2 * cw + 32 * j;
        float bx = bias[c], by = bias[c + 1];
#pragma unroll
        for (int i = 0; i < 4; i++) {
            float lo, hi;
            unpack2(acc[i][j], lo, hi);
            lo += bx; hi += by;
            if (RELU) { lo = fmaxf(lo, 0.f); hi = fmaxf(hi, 0.f); }
            *(float2*)(Out + (r0 + i) * OUTS + c) = make_float2(lo, hi);
        }
    }
    __syncthreads();
}

__global__ void __launch_bounds__(256, 1) edge_kernel(
    const float* __restrict__ x, const float* __restrict__ eattr,
    const float* __restrict__ u, const int* __restrict__ ei,
    const int* __restrict__ batch,
    const float* __restrict__ ew1, const float* __restrict__ eb1,
    const float* __restrict__ ewh, const float* __restrict__ ebh,
    const float* __restrict__ ew2, const float* __restrict__ eb2,
    const float* __restrict__ eg,  const float* __restrict__ ebt,
    const float* __restrict__ aw1, const float* __restrict__ ab1,
    const float* __restrict__ awh, const float* __restrict__ abh,
    const float* __restrict__ aw2, const float* __restrict__ ab2,
    const float* __restrict__ ag,  const float* __restrict__ abt)
{
    extern __shared__ float sm[];
    float* Xs = sm;                    // 64 x 212
    float* Ha = Xs + 64 * 212;         // 64 x 132
    float* Hb = Ha + 64 * 132;         // 64 x 132
    float* Eo = Hb + 64 * 132;         // 64 x 68
    float* Ao = Eo + 64 * 68;          // 64 x 68
    float* Wp = Ao + 64 * 68;          // 2 x 16 x 128
    int* srcs = (int*)(Wp + 2 * 16 * 128);
    int* tgts = srcs + 64;
    int* ebs  = tgts + 64;

    const int tid = threadIdx.x;
    const int e0 = blockIdx.x * 64;

    if (tid < 64) {
        int s = ei[e0 + tid];
        int t = ei[N_EDGES + e0 + tid];
        srcs[tid] = s; tgts[tid] = t; ebs[tid] = batch[s];
    }
    __syncthreads();

    const float4* x4  = (const float4*)x;
    const float4* ea4 = (const float4*)eattr;
    const float4* u4  = (const float4*)u;
    for (int i = tid; i < 64 * 52; i += 256) {
        int e = i / 52, q = i - e * 52;
        float4 v;
        if (q < 16)      v = x4[(size_t)srcs[e] * 16 + q];
        else if (q < 32) v = x4[(size_t)tgts[e] * 16 + (q - 16)];
        else if (q < 48) v = ea4[(size_t)(e0 + e) * 16 + (q - 32)];
        else             v = u4[(size_t)ebs[e] * 4 + (q - 48)];
        *(float4*)(Xs + e * 212 + q * 4) = v;
    }
    __syncthreads();

    gemm_layer<208, 128, 212, 132, true >(ew1, eb1, Xs, Ha, Wp, tid);
    gemm_layer<128, 128, 132, 132, true >(ewh, ebh, Ha, Hb, Wp, tid);
    gemm_layer<128, 128, 132, 132, true >(ewh + 128 * 128, ebh + 128, Hb, Ha, Wp, tid);
    gemm_layer<128,  64, 132,  68, false>(ew2, eb2, Ha, Eo, Wp, tid);

    gemm_layer<208, 128, 212, 132, true >(aw1, ab1, Xs, Ha, Wp, tid);
    gemm_layer<128, 128, 132, 132, true >(awh, abh, Ha, Hb, Wp, tid);
    gemm_layer<128, 128, 132, 132, true >(awh + 128 * 128, abh + 128, Hb, Ha, Wp, tid);
    gemm_layer<128,  64, 132,  68, false>(aw2, ab2, Ha, Ao, Wp, tid);

    const int e  = tid >> 2;
    const int cb = (tid & 3) * 16;
    float s1 = 0.f, s2 = 0.f, t1 = 0.f, t2 = 0.f;
#pragma unroll
    for (int cc = 0; cc < 16; cc++) {
        float ve = Eo[e * 68 + cb + cc]; s1 += ve; s2 += ve * ve;
        float va = Ao[e * 68 + cb + cc]; t1 += va; t2 += va * va;
    }
#pragma unroll
    for (int off = 1; off < 4; off <<= 1) {
        s1 += __shfl_xor_sync(0xffffffffu, s1, off);
        s2 += __shfl_xor_sync(0xffffffffu, s2, off);
        t1 += __shfl_xor_sync(0xffffffffu, t1, off);
        t2 += __shfl_xor_sync(0xffffffffu, t2, off);
    }
    float mue = s1 * (1.f / 64.f), mua = t1 * (1.f / 64.f);
    float rse = rsqrtf(fmaxf(s2 * (1.f / 64.f) - mue * mue, 0.f) + 1e-5f);
    float rsa = rsqrtf(fmaxf(t2 * (1.f / 64.f) - mua * mua, 0.f) + 1e-5f);

    float* arow = g_agg + (size_t)tgts[e] * 64;
#pragma unroll
    for (int cc = 0; cc < 16; cc++) {
        int c = cb + cc;
        float fe = (Eo[e * 68 + c] - mue) * rse * eg[c] + ebt[c];
        float fa = (Ao[e * 68 + c] - mua) * rsa * ag[c] + abt[c];
        float sg = 1.f / (1.f + expf(-fa));
        atomicAdd(arow + c, fe * sg);
    }
}

__global__ void __launch_bounds__(256, 1) node_kernel(
    const float* __restrict__ x, const float* __restrict__ u,
    const int* __restrict__ batch,
    const float* __restrict__ nw1, const float* __restrict__ nb1,
    const float* __restrict__ nwh, const float* __restrict__ nbh,
    const float* __restrict__ nw2, const float* __restrict__ nb2,
    const float* __restrict__ ng,  const float* __restrict__ nbt,
    float* __restrict__ out)
{
    extern __shared__ float sm[];
    float* Xs = sm;                    // 64 x 148
    float* Ha = Xs + 64 * 148;
    float* Hb = Ha + 64 * 132;
    float* Eo = Hb + 64 * 132;         // 64 x 68
    float* Wp = Eo + 64 * 68;          // 2 x 16 x 128
    int* bts  = (int*)(Wp + 2 * 16 * 128);

    const int tid = threadIdx.x;
    const int n0 = blockIdx.x * 64;

    if (tid < 64) {
        int n = n0 + tid;
        bts[tid] = (n < N_NODES) ? batch[n] : 0;
    }
    __syncthreads();

    const float4* x4  = (const float4*)x;
    const float4* ag4 = (const float4*)g_agg;
    const float4* u4  = (const float4*)u;
    for (int i = tid; i < 64 * 36; i += 256) {
        int e = i / 36, q = i - e * 36;
        int n = n0 + e;
        float4 v = make_float4(0.f, 0.f, 0.f, 0.f);
        if (n < N_NODES) {
            if (q < 16)      v = x4[(size_t)n * 16 + q];
            else if (q < 32) v = ag4[(size_t)n * 16 + (q - 16)];
            else             v = u4[(size_t)bts[e] * 4 + (q - 32)];
        }
        *(float4*)(Xs + e * 148 + q * 4) = v;
    }
    __syncthreads();

    gemm_layer<144, 128, 148, 132, true >(nw1, nb1, Xs, Ha, Wp, tid);
    gemm_layer<128, 128, 132, 132, true >(nwh, nbh, Ha, Hb, Wp, tid);
    gemm_layer<128, 128, 132, 132, true >(nwh + 128 * 128, nbh + 128, Hb, Ha, Wp, tid);
    gemm_layer<128,  64, 132,  68, false>(nw2, nb2, Ha, Eo, Wp, tid);

    const int e  = tid >> 2;
    const int cb = (tid & 3) * 16;
    float s1 = 0.f, s2 = 0.f;
#pragma unroll
    for (int cc = 0; cc < 16; cc++) {
        float v = Eo[e * 68 + cb + cc]; s1 += v; s2 += v * v;
    }
#pragma unroll
    for (int off = 1; off < 4; off <<= 1) {
        s1 += __shfl_xor_sync(0xffffffffu, s1, off);
        s2 += __shfl_xor_sync(0xffffffffu, s2, off);
    }
    float mu = s1 * (1.f / 64.f);
    float rs = rsqrtf(fmaxf(s2 * (1.f / 64.f) - mu * mu, 0.f) + 1e-5f);

    int n = n0 + e;
    if (n < N_NODES) {
#pragma unroll
        for (int cc = 0; cc < 16; cc++) {
            int c = cb + cc;
            out[(size_t)n * 64 + c] = (Eo[e * 68 + c] - mu) * rs * ng[c] + nbt[c];
        }
    }
}

extern "C" void kernel_launch(void* const* d_in, const int* in_sizes, int n_in,
                              void* d_out, int out_size)
{
    const float* x     = (const float*)d_in[0];
    const float* eattr = (const float*)d_in[1];
    const float* u     = (const float*)d_in[2];
    const int*   ei    = (const int*)d_in[3];
    const int*   batch = (const int*)d_in[4];
    const float* ew1 = (const float*)d_in[5],  *eb1 = (const float*)d_in[6];
    const float* ewh = (const float*)d_in[7],  *ebh = (const float*)d_in[8];
    const float* ew2 = (const float*)d_in[9],  *eb2 = (const float*)d_in[10];
    const float* eg  = (const float*)d_in[11], *ebt = (const float*)d_in[12];
    const float* aw1 = (const float*)d_in[13], *ab1 = (const float*)d_in[14];
    const float* awh = (const float*)d_in[15], *abh = (const float*)d_in[16];
    const float* aw2 = (const float*)d_in[17], *ab2 = (const float*)d_in[18];
    const float* ag  = (const float*)d_in[19], *abt = (const float*)d_in[20];
    const float* nw1 = (const float*)d_in[21], *nb1 = (const float*)d_in[22];
    const float* nwh = (const float*)d_in[23], *nbh = (const float*)d_in[24];
    const float* nw2 = (const float*)d_in[25], *nb2 = (const float*)d_in[26];
    const float* ng  = (const float*)d_in[27], *nbt = (const float*)d_in[28];
    float* out = (float*)d_out;

    static bool attr_done = false;
    size_t smem_edge = (size_t)(64 * 212 + 2 * 64 * 132 + 2 * 64 * 68 + 2 * 16 * 128) * 4 + 3 * 64 * 4;
    size_t smem_node = (size_t)(64 * 148 + 2 * 64 * 132 + 64 * 68 + 2 * 16 * 128) * 4 + 64 * 4;
    cudaFuncSetAttribute(edge_kernel, cudaFuncAttributeMaxDynamicSharedMemorySize, (int)smem_edge);
    cudaFuncSetAttribute(node_kernel, cudaFuncAttributeMaxDynamicSharedMemorySize, (int)smem_node);
    (void)attr_done; (void)in_sizes; (void)n_in; (void)out_size;

    void* aggp = nullptr;
    cudaGetSymbolAddress(&aggp, g_agg);
    cudaMemsetAsync(aggp, 0, sizeof(float) * (size_t)N_NODES * 64, 0);

    edge_kernel<<<N_EDGES / 64, 256, smem_edge>>>(
        x, eattr, u, ei, batch,
        ew1, eb1, ewh, ebh, ew2, eb2, eg, ebt,
        aw1, ab1, awh, abh, aw2, ab2, ag, abt);

    node_kernel<<<(N_NODES + 63) / 64, 256, smem_node>>>(
        x, u, batch, nw1, nb1, nwh, nbh, nw2, nb2, ng, nbt, out);
}

// round 4
// speedup vs baseline: 2.7682x; 2.7682x over previous
#include <cuda_runtime.h>
#include <cuda_bf16.h>
#include <cstdint>
#include <math.h>

#define N_NODES 50000
#define N_EDGES 400000

// ---------------- device scratch ----------------
__device__ float g_agg[(size_t)N_NODES * 64];
__device__ __align__(128) unsigned char g_wimg[778240];

// layer image bases (interleaved hi/lo panels per 16-row unit)
#define EDGE_UNITS 74
#define NODE_UNITS 33
#define NODE_BASE  540672u

// ---------------- low-level helpers ----------------
__device__ __forceinline__ uint32_t smem_u32(const void* p) {
    uint32_t a;
    asm("{ .reg .u64 t; cvta.to.shared.u64 t, %1; cvt.u32.u64 %0, t; }" : "=r"(a) : "l"(p));
    return a;
}
__device__ __forceinline__ void cp16(uint32_t dst, const void* src) {
    asm volatile("cp.async.cg.shared.global [%0], [%1], 16;" :: "r"(dst), "l"(src) : "memory");
}
__device__ __forceinline__ void cp_commit() { asm volatile("cp.async.commit_group;" ::: "memory"); }
__device__ __forceinline__ void cp_wait2()  { asm volatile("cp.async.wait_group 2;" ::: "memory"); }

__device__ __forceinline__ void ldsm4t(uint32_t* r, uint32_t addr) {
    asm volatile("ldmatrix.sync.aligned.m8n8.x4.trans.shared.b16 {%0,%1,%2,%3}, [%4];"
        : "=r"(r[0]), "=r"(r[1]), "=r"(r[2]), "=r"(r[3]) : "r"(addr));
}
__device__ __forceinline__ void hmma(float* c, const uint32_t* a, uint32_t b0, uint32_t b1) {
    asm volatile("mma.sync.aligned.m16n8k16.row.col.f32.bf16.bf16.f32 "
        "{%0,%1,%2,%3}, {%4,%5,%6,%7}, {%8,%9}, {%0,%1,%2,%3};"
        : "+f"(c[0]), "+f"(c[1]), "+f"(c[2]), "+f"(c[3])
        : "r"(a[0]), "r"(a[1]), "r"(a[2]), "r"(a[3]), "r"(b0), "r"(b1));
}
__device__ __forceinline__ void split2(float a, float b, uint32_t& h, uint32_t& l) {
    __nv_bfloat162 hb = __floats2bfloat162_rn(a, b);
    float ra = a - __bfloat162float(__low2bfloat16(hb));
    float rb = b - __bfloat162float(__high2bfloat16(hb));
    __nv_bfloat162 lb = __floats2bfloat162_rn(ra, rb);
    h = *reinterpret_cast<uint32_t*>(&hb);
    l = *reinterpret_cast<uint32_t*>(&lb);
}

// ---------------- weight-stream pipeline ----------------
struct Pipe {
    uint32_t swaddr;            // stage buffer base (4 x 8192)
    const uint32_t* srcOff;     // per-unit source offset into region
    const uint16_t* chunks;     // per-unit 16B-chunk count
    const unsigned char* base;  // g_wimg region base
    int nU;
    int u;
    int tid;
};
__device__ __forceinline__ void pipe_issue(Pipe& p, int v) {
    if (v < p.nU) {
        uint32_t dst = p.swaddr + (uint32_t)(v & 3) * 8192u;
        const unsigned char* src = p.base + p.srcOff[v];
        int nc = p.chunks[v];
        for (int c = p.tid; c < nc; c += 256)
            cp16(dst + (uint32_t)c * 16u, src + (size_t)c * 16u);
    }
    cp_commit();
}
__device__ __forceinline__ uint32_t pipe_acquire(Pipe& p) {
    cp_wait2();
    __syncthreads();
    pipe_issue(p, p.u + 3);
    uint32_t s = p.swaddr + (uint32_t)(p.u & 3) * 8192u;
    p.u++;
    return s;
}

// ---------------- MMA tile: 3-term split, one 16-k panel ----------------
template<int NT>
__device__ __forceinline__ void mma_tile(float (*acc)[4], const uint32_t* ah, const uint32_t* al,
                                         uint32_t stage, int lane) {
    const int i = lane & 7, m = lane >> 3;
    const int row = ((m & 1) << 3) + i;
    const uint32_t rowoff = (uint32_t)row * (2 * NT);
    const int gsel = m >> 1;
#pragma unroll
    for (int j = 0; j < NT / 16; j++) {
        uint32_t ga = stage + rowoff + (uint32_t)((((2 * j + gsel) ^ i)) << 4);
        uint32_t bh[4]; ldsm4t(bh, ga);
        hmma(acc[2 * j],     ah, bh[0], bh[1]);
        hmma(acc[2 * j + 1], ah, bh[2], bh[3]);
        hmma(acc[2 * j],     al, bh[0], bh[1]);
        hmma(acc[2 * j + 1], al, bh[2], bh[3]);
        uint32_t bl[4]; ldsm4t(bl, ga + NT * 32);
        hmma(acc[2 * j],     ah, bl[0], bl[1]);
        hmma(acc[2 * j + 1], ah, bl[2], bl[3]);
    }
}

__device__ __forceinline__ void zero_acc(float (*acc)[4], int nt) {
#pragma unroll
    for (int j = 0; j < 16; j++)
        if (j < nt) { acc[j][0] = 0.f; acc[j][1] = 0.f; acc[j][2] = 0.f; acc[j][3] = 0.f; }
}

// bias + relu + bf16-split: acc[16][4] (N=128) -> A frags for next layer (K=128)
__device__ __forceinline__ void epi_relu128(const float (*acc)[4], const float* __restrict__ bias,
                                            uint32_t (*Ahi)[4], uint32_t (*Alo)[4], int q) {
#pragma unroll
    for (int t = 0; t < 8; t++) {
        float2 b0 = *(const float2*)(bias + 16 * t + 2 * q);
        float2 b1 = *(const float2*)(bias + 16 * t + 8 + 2 * q);
        float v00 = fmaxf(acc[2 * t][0] + b0.x, 0.f), v01 = fmaxf(acc[2 * t][1] + b0.y, 0.f);
        float v10 = fmaxf(acc[2 * t][2] + b0.x, 0.f), v11 = fmaxf(acc[2 * t][3] + b0.y, 0.f);
        float v20 = fmaxf(acc[2 * t + 1][0] + b1.x, 0.f), v21 = fmaxf(acc[2 * t + 1][1] + b1.y, 0.f);
        float v30 = fmaxf(acc[2 * t + 1][2] + b1.x, 0.f), v31 = fmaxf(acc[2 * t + 1][3] + b1.y, 0.f);
        split2(v00, v01, Ahi[t][0], Alo[t][0]);
        split2(v10, v11, Ahi[t][1], Alo[t][1]);
        split2(v20, v21, Ahi[t][2], Alo[t][2]);
        split2(v30, v31, Ahi[t][3], Alo[t][3]);
    }
}

// bias + LayerNorm stats over 64 cols (N=64). vv = biased values; quad shfl reduce.
__device__ __forceinline__ void ln_stats(const float (*acc)[4], const float* __restrict__ bias, int q,
                                         float (*vv)[4], float& muA, float& rsA, float& muB, float& rsB) {
    float sA = 0.f, sA2 = 0.f, sB = 0.f, sB2 = 0.f;
#pragma unroll
    for (int j = 0; j < 8; j++) {
        float2 b = *(const float2*)(bias + 8 * j + 2 * q);
        float v0 = acc[j][0] + b.x, v1 = acc[j][1] + b.y;
        float v2 = acc[j][2] + b.x, v3 = acc[j][3] + b.y;
        vv[j][0] = v0; vv[j][1] = v1; vv[j][2] = v2; vv[j][3] = v3;
        sA += v0 + v1; sA2 += v0 * v0 + v1 * v1;
        sB += v2 + v3; sB2 += v2 * v2 + v3 * v3;
    }
#pragma unroll
    for (int o = 1; o < 4; o <<= 1) {
        sA  += __shfl_xor_sync(0xffffffffu, sA, o);
        sA2 += __shfl_xor_sync(0xffffffffu, sA2, o);
        sB  += __shfl_xor_sync(0xffffffffu, sB, o);
        sB2 += __shfl_xor_sync(0xffffffffu, sB2, o);
    }
    muA = sA * (1.f / 64.f);
    rsA = rsqrtf(fmaxf(sA2 * (1.f / 64.f) - muA * muA, 0.f) + 1e-5f);
    muB = sB * (1.f / 64.f);
    rsB = rsqrtf(fmaxf(sB2 * (1.f / 64.f) - muB * muB, 0.f) + 1e-5f);
}

// ---------------------------------------------------------------------------
// prep kernel: fp32 weights -> bf16 hi/lo, pre-swizzled, panel-interleaved
// ---------------------------------------------------------------------------
__global__ void prep_kernel(const float* ew1, const float* ewh, const float* ew2,
                            const float* aw1, const float* awh, const float* aw2,
                            const float* nw1, const float* nwh, const float* nw2)
{
    const int K[12]  = {208,128,128,128, 208,128,128,128, 144,128,128,128};
    const int N[12]  = {128,128,128,64,  128,128,128,64,  128,128,128,64};
    const uint32_t BASE[12] = {0,106496,172032,237568, 270336,376832,442368,507904,
                               540672,614400,679936,745472};
    const int CNT[12] = {26624,16384,16384,8192, 26624,16384,16384,8192, 18432,16384,16384,8192};
    const float* SRC[12] = {ew1, ewh, ewh + 16384, ew2, aw1, awh, awh + 16384, aw2,
                            nw1, nwh, nwh + 16384, nw2};

    int idx = blockIdx.x * blockDim.x + threadIdx.x;
    if (idx >= 194560) return;
    int t = 0, accu = 0;
    while (idx >= accu + CNT[t]) { accu += CNT[t]; t++; }
    int loc = idx - accu;
    int n = loc % N[t], k = loc / N[t];
    float v = SRC[t][(size_t)k * N[t] + n];
    __nv_bfloat16 h = __float2bfloat16(v);
    __nv_bfloat16 l = __float2bfloat16(v - __bfloat162float(h));
    uint32_t pb = (uint32_t)N[t] * 32u;                    // panel bytes
    uint32_t off = BASE[t] + (uint32_t)(k >> 4) * (pb * 2u)
                 + (uint32_t)(k & 15) * (uint32_t)(2 * N[t])
                 + (uint32_t)((((n >> 3) ^ (k & 7))) << 4) + (uint32_t)(n & 7) * 2u;
    *(__nv_bfloat16*)(g_wimg + off) = h;
    *(__nv_bfloat16*)(g_wimg + off + pb) = l;
}

// ---------------------------------------------------------------------------
// edge kernel
// ---------------------------------------------------------------------------
__device__ __forceinline__ const float* eptr(int c, int row,
    const float* __restrict__ x, const float* __restrict__ ea, const float* __restrict__ u,
    const int* srcs, const int* tgts, const int* ebs, int e0) {
    if (c < 64)  return x  + (size_t)srcs[row] * 64 + c;
    if (c < 128) return x  + (size_t)tgts[row] * 64 + (c - 64);
    if (c < 192) return ea + (size_t)(e0 + row) * 64 + (c - 128);
    return u + (size_t)ebs[row] * 16 + (c - 192);
}

__global__ void __launch_bounds__(256, 1) edge_kernel(
    const float* __restrict__ x, const float* __restrict__ eattr,
    const float* __restrict__ u, const int* __restrict__ ei, const int* __restrict__ batch,
    const float* __restrict__ eb1, const float* __restrict__ ebh, const float* __restrict__ eb2,
    const float* __restrict__ eg,  const float* __restrict__ ebt,
    const float* __restrict__ ab1, const float* __restrict__ abh, const float* __restrict__ ab2,
    const float* __restrict__ ag,  const float* __restrict__ abt)
{
    __shared__ __align__(128) unsigned char sW[4 * 8192];
    __shared__ uint32_t sSrc[EDGE_UNITS];
    __shared__ uint16_t sChk[EDGE_UNITS];
    __shared__ int sIdx[3 * 128];

    const int tid = threadIdx.x;
    const int lane = tid & 31, warp = tid >> 5;
    const int q = lane & 3, rloc = lane >> 2;
    const int rA = warp * 16 + rloc, rB = rA + 8;
    const int e0 = blockIdx.x * 128;

    int* srcs = sIdx; int* tgts = sIdx + 128; int* ebs = sIdx + 256;
    if (tid < 128) {
        int s = ei[e0 + tid];
        int t = ei[N_EDGES + e0 + tid];
        srcs[tid] = s; tgts[tid] = t; ebs[tid] = batch[s];
    }
    if (tid == 0) {
        const int LU[8]  = {13, 8, 8, 8, 13, 8, 8, 8};
        const int LPB[8] = {4096, 4096, 4096, 2048, 4096, 4096, 4096, 2048};
        uint32_t off = 0; int uu = 0;
        for (int l = 0; l < 8; l++)
            for (int t = 0; t < LU[l]; t++) {
                sSrc[uu] = off; sChk[uu] = (uint16_t)((2 * LPB[l]) >> 4);
                off += 2 * LPB[l]; uu++;
            }
    }
    __syncthreads();

    Pipe p; p.swaddr = smem_u32(sW); p.srcOff = sSrc; p.chunks = sChk;
    p.base = g_wimg; p.nU = EDGE_UNITS; p.u = 0; p.tid = tid;
    pipe_issue(p, 0); pipe_issue(p, 1); pipe_issue(p, 2);

    float acc[16][4];
    uint32_t Ahi[8][4], Alo[8][4];
    float eo[8][4];

    const float* B1[2] = {eb1, ab1};
    const float* BH[2] = {ebh, abh};
    const float* B2[2] = {eb2, ab2};

    for (int mlp = 0; mlp < 2; mlp++) {
        // layer 0: K=208, gather A per tile
        zero_acc(acc, 16);
        for (int t = 0; t < 13; t++) {
            uint32_t ah4[4], al4[4];
            int c0 = 16 * t + 2 * q;
            float2 f0 = *(const float2*)eptr(c0,     rA, x, eattr, u, srcs, tgts, ebs, e0);
            float2 f1 = *(const float2*)eptr(c0,     rB, x, eattr, u, srcs, tgts, ebs, e0);
            float2 f2 = *(const float2*)eptr(c0 + 8, rA, x, eattr, u, srcs, tgts, ebs, e0);
            float2 f3 = *(const float2*)eptr(c0 + 8, rB, x, eattr, u, srcs, tgts, ebs, e0);
            split2(f0.x, f0.y, ah4[0], al4[0]);
            split2(f1.x, f1.y, ah4[1], al4[1]);
            split2(f2.x, f2.y, ah4[2], al4[2]);
            split2(f3.x, f3.y, ah4[3], al4[3]);
            uint32_t st = pipe_acquire(p);
            mma_tile<128>(acc, ah4, al4, st, lane);
        }
        epi_relu128(acc, B1[mlp], Ahi, Alo, q);

        // hidden layers 1,2: K=128,N=128
        for (int hl = 0; hl < 2; hl++) {
            zero_acc(acc, 16);
            for (int t = 0; t < 8; t++) {
                uint32_t st = pipe_acquire(p);
                mma_tile<128>(acc, Ahi[t], Alo[t], st, lane);
            }
            epi_relu128(acc, BH[mlp] + hl * 128, Ahi, Alo, q);
        }

        // out layer: K=128,N=64 -> LN
        zero_acc(acc, 8);
        for (int t = 0; t < 8; t++) {
            uint32_t st = pipe_acquire(p);
            mma_tile<64>(acc, Ahi[t], Alo[t], st, lane);
        }
        float vv[8][4], muA, rsA, muB, rsB;
        ln_stats(acc, B2[mlp], q, vv, muA, rsA, muB, rsB);
        if (mlp == 0) {
#pragma unroll
            for (int j = 0; j < 8; j++) {
                int c = 8 * j + 2 * q;
                float2 gm = *(const float2*)(eg + c);
                float2 bt = *(const float2*)(ebt + c);
                eo[j][0] = (vv[j][0] - muA) * rsA * gm.x + bt.x;
                eo[j][1] = (vv[j][1] - muA) * rsA * gm.y + bt.y;
                eo[j][2] = (vv[j][2] - muB) * rsB * gm.x + bt.x;
                eo[j][3] = (vv[j][3] - muB) * rsB * gm.y + bt.y;
            }
        } else {
            float* rowP_A = g_agg + (size_t)tgts[rA] * 64;
            float* rowP_B = g_agg + (size_t)tgts[rB] * 64;
#pragma unroll
            for (int j = 0; j < 8; j++) {
                int c = 8 * j + 2 * q;
                float2 gm = *(const float2*)(ag + c);
                float2 bt = *(const float2*)(abt + c);
                float a0 = (vv[j][0] - muA) * rsA * gm.x + bt.x;
                float a1 = (vv[j][1] - muA) * rsA * gm.y + bt.y;
                float a2 = (vv[j][2] - muB) * rsB * gm.x + bt.x;
                float a3 = (vv[j][3] - muB) * rsB * gm.y + bt.y;
                atomicAdd(rowP_A + c,     eo[j][0] / (1.f + expf(-a0)));
                atomicAdd(rowP_A + c + 1, eo[j][1] / (1.f + expf(-a1)));
                atomicAdd(rowP_B + c,     eo[j][2] / (1.f + expf(-a2)));
                atomicAdd(rowP_B + c + 1, eo[j][3] / (1.f + expf(-a3)));
            }
        }
    }
}

// ---------------------------------------------------------------------------
// node kernel
// ---------------------------------------------------------------------------
__device__ __forceinline__ const float* nptr(int c, int n, int bt,
    const float* __restrict__ x, const float* __restrict__ u) {
    if (c < 64)  return x + (size_t)n * 64 + c;
    if (c < 128) return g_agg + (size_t)n * 64 + (c - 64);
    return u + (size_t)bt * 16 + (c - 128);
}

__global__ void __launch_bounds__(256, 1) node_kernel(
    const float* __restrict__ x, const float* __restrict__ u, const int* __restrict__ batch,
    const float* __restrict__ nb1, const float* __restrict__ nbh, const float* __restrict__ nb2,
    const float* __restrict__ ng,  const float* __restrict__ nbt,
    float* __restrict__ out)
{
    __shared__ __align__(128) unsigned char sW[4 * 8192];
    __shared__ uint32_t sSrc[NODE_UNITS];
    __shared__ uint16_t sChk[NODE_UNITS];
    __shared__ int sBt[128];

    const int tid = threadIdx.x;
    const int lane = tid & 31, warp = tid >> 5;
    const int q = lane & 3, rloc = lane >> 2;
    const int rA = warp * 16 + rloc, rB = rA + 8;
    const int n0 = blockIdx.x * 128;

    if (tid < 128) {
        int n = n0 + tid;
        sBt[tid] = (n < N_NODES) ? batch[n] : 0;
    }
    if (tid == 0) {
        const int LU[4]  = {9, 8, 8, 8};
        const int LPB[4] = {4096, 4096, 4096, 2048};
        uint32_t off = 0; int uu = 0;
        for (int l = 0; l < 4; l++)
            for (int t = 0; t < LU[l]; t++) {
                sSrc[uu] = off; sChk[uu] = (uint16_t)((2 * LPB[l]) >> 4);
                off += 2 * LPB[l]; uu++;
            }
    }
    __syncthreads();

    Pipe p; p.swaddr = smem_u32(sW); p.srcOff = sSrc; p.chunks = sChk;
    p.base = g_wimg + NODE_BASE; p.nU = NODE_UNITS; p.u = 0; p.tid = tid;
    pipe_issue(p, 0); pipe_issue(p, 1); pipe_issue(p, 2);

    const int nA = (n0 + rA < N_NODES) ? n0 + rA : N_NODES - 1;
    const int nB = (n0 + rB < N_NODES) ? n0 + rB : N_NODES - 1;
    const int btA = sBt[rA], btB = sBt[rB];

    float acc[16][4];
    uint32_t Ahi[8][4], Alo[8][4];

    // layer 0: K=144, gather per tile
    zero_acc(acc, 16);
    for (int t = 0; t < 9; t++) {
        uint32_t ah4[4], al4[4];
        int c0 = 16 * t + 2 * q;
        float2 f0 = *(const float2*)nptr(c0,     nA, btA, x, u);
        float2 f1 = *(const float2*)nptr(c0,     nB, btB, x, u);
        float2 f2 = *(const float2*)nptr(c0 + 8, nA, btA, x, u);
        float2 f3 = *(const float2*)nptr(c0 + 8, nB, btB, x, u);
        split2(f0.x, f0.y, ah4[0], al4[0]);
        split2(f1.x, f1.y, ah4[1], al4[1]);
        split2(f2.x, f2.y, ah4[2], al4[2]);
        split2(f3.x, f3.y, ah4[3], al4[3]);
        uint32_t st = pipe_acquire(p);
        mma_tile<128>(acc, ah4, al4, st, lane);
    }
    epi_relu128(acc, nb1, Ahi, Alo, q);

    for (int hl = 0; hl < 2; hl++) {
        zero_acc(acc, 16);
        for (int t = 0; t < 8; t++) {
            uint32_t st = pipe_acquire(p);
            mma_tile<128>(acc, Ahi[t], Alo[t], st, lane);
        }
        epi_relu128(acc, nbh + hl * 128, Ahi, Alo, q);
    }

    zero_acc(acc, 8);
    for (int t = 0; t < 8; t++) {
        uint32_t st = pipe_acquire(p);
        mma_tile<64>(acc, Ahi[t], Alo[t], st, lane);
    }
    float vv[8][4], muA, rsA, muB, rsB;
    ln_stats(acc, nb2, q, vv, muA, rsA, muB, rsB);

    const bool vA = (n0 + rA < N_NODES), vB = (n0 + rB < N_NODES);
#pragma unroll
    for (int j = 0; j < 8; j++) {
        int c = 8 * j + 2 * q;
        float2 gm = *(const float2*)(ng + c);
        float2 bt = *(const float2*)(nbt + c);
        if (vA) {
            float2 o; o.x = (vv[j][0] - muA) * rsA * gm.x + bt.x;
            o.y = (vv[j][1] - muA) * rsA * gm.y + bt.y;
            *(float2*)(out + (size_t)(n0 + rA) * 64 + c) = o;
        }
        if (vB) {
            float2 o; o.x = (vv[j][2] - muB) * rsB * gm.x + bt.x;
            o.y = (vv[j][3] - muB) * rsB * gm.y + bt.y;
            *(float2*)(out + (size_t)(n0 + rB) * 64 + c) = o;
        }
    }
}

// ---------------------------------------------------------------------------
extern "C" void kernel_launch(void* const* d_in, const int* in_sizes, int n_in,
                              void* d_out, int out_size)
{
    const float* x     = (const float*)d_in[0];
    const float* eattr = (const float*)d_in[1];
    const float* u     = (const float*)d_in[2];
    const int*   ei    = (const int*)d_in[3];
    const int*   batch = (const int*)d_in[4];
    const float* ew1 = (const float*)d_in[5],  *eb1 = (const float*)d_in[6];
    const float* ewh = (const float*)d_in[7],  *ebh = (const float*)d_in[8];
    const float* ew2 = (const float*)d_in[9],  *eb2 = (const float*)d_in[10];
    const float* eg  = (const float*)d_in[11], *ebt = (const float*)d_in[12];
    const float* aw1 = (const float*)d_in[13], *ab1 = (const float*)d_in[14];
    const float* awh = (const float*)d_in[15], *abh = (const float*)d_in[16];
    const float* aw2 = (const float*)d_in[17], *ab2 = (const float*)d_in[18];
    const float* ag  = (const float*)d_in[19], *abt = (const float*)d_in[20];
    const float* nw1 = (const float*)d_in[21], *nb1 = (const float*)d_in[22];
    const float* nwh = (const float*)d_in[23], *nbh = (const float*)d_in[24];
    const float* nw2 = (const float*)d_in[25], *nb2 = (const float*)d_in[26];
    const float* ng  = (const float*)d_in[27], *nbt = (const float*)d_in[28];
    float* out = (float*)d_out;
    (void)in_sizes; (void)n_in; (void)out_size;

    void* aggp = nullptr;
    cudaGetSymbolAddress(&aggp, g_agg);
    cudaMemsetAsync(aggp, 0, sizeof(float) * (size_t)N_NODES * 64, 0);

    prep_kernel<<<(194560 + 255) / 256, 256>>>(ew1, ewh, ew2, aw1, awh, aw2, nw1, nwh, nw2);

    edge_kernel<<<N_EDGES / 128, 256>>>(
        x, eattr, u, ei, batch,
        eb1, ebh, eb2, eg, ebt,
        ab1, abh, ab2, ag, abt);

    node_kernel<<<(N_NODES + 127) / 128, 256>>>(
        x, u, batch, nb1, nbh, nb2, ng, nbt, out);
}

// round 5
// speedup vs baseline: 3.0893x; 1.1160x over previous
#include <cuda_runtime.h>
#include <cuda_bf16.h>
#include <cstdint>
#include <math.h>

#define N_NODES 50000
#define N_EDGES 400000

// ---------------- device scratch ----------------
__device__ float g_agg[(size_t)N_NODES * 64];
__device__ __align__(128) unsigned char g_wimg[778240];

#define EDGE_UNITS 74
#define NODE_UNITS 33
#define NODE_BASE  540672u
#define BLK 128

// ---------------- low-level helpers ----------------
__device__ __forceinline__ uint32_t smem_u32(const void* p) {
    uint32_t a;
    asm("{ .reg .u64 t; cvta.to.shared.u64 t, %1; cvt.u32.u64 %0, t; }" : "=r"(a) : "l"(p));
    return a;
}
__device__ __forceinline__ void cp16(uint32_t dst, const void* src) {
    asm volatile("cp.async.cg.shared.global [%0], [%1], 16;" :: "r"(dst), "l"(src) : "memory");
}
__device__ __forceinline__ void cp_commit() { asm volatile("cp.async.commit_group;" ::: "memory"); }
__device__ __forceinline__ void cp_wait2()  { asm volatile("cp.async.wait_group 2;" ::: "memory"); }

__device__ __forceinline__ void ldsm4t(uint32_t* r, uint32_t addr) {
    asm volatile("ldmatrix.sync.aligned.m8n8.x4.trans.shared.b16 {%0,%1,%2,%3}, [%4];"
        : "=r"(r[0]), "=r"(r[1]), "=r"(r[2]), "=r"(r[3]) : "r"(addr));
}
__device__ __forceinline__ void hmma(float* c, const uint32_t* a, uint32_t b0, uint32_t b1) {
    asm volatile("mma.sync.aligned.m16n8k16.row.col.f32.bf16.bf16.f32 "
        "{%0,%1,%2,%3}, {%4,%5,%6,%7}, {%8,%9}, {%0,%1,%2,%3};"
        : "+f"(c[0]), "+f"(c[1]), "+f"(c[2]), "+f"(c[3])
        : "r"(a[0]), "r"(a[1]), "r"(a[2]), "r"(a[3]), "r"(b0), "r"(b1));
}
__device__ __forceinline__ void split2(float a, float b, uint32_t& h, uint32_t& l) {
    __nv_bfloat162 hb = __floats2bfloat162_rn(a, b);
    float ra = a - __bfloat162float(__low2bfloat16(hb));
    float rb = b - __bfloat162float(__high2bfloat16(hb));
    __nv_bfloat162 lb = __floats2bfloat162_rn(ra, rb);
    h = *reinterpret_cast<uint32_t*>(&hb);
    l = *reinterpret_cast<uint32_t*>(&lb);
}

// ---------------- weight-stream pipeline ----------------
struct Pipe {
    uint32_t swaddr;
    const uint32_t* srcOff;
    const uint16_t* chunks;
    const unsigned char* base;
    int nU;
    int u;
    int tid;
};
__device__ __forceinline__ void pipe_issue(Pipe& p, int v) {
    if (v < p.nU) {
        uint32_t dst = p.swaddr + (uint32_t)(v & 3) * 8192u;
        const unsigned char* src = p.base + p.srcOff[v];
        int nc = p.chunks[v];
        for (int c = p.tid; c < nc; c += BLK)
            cp16(dst + (uint32_t)c * 16u, src + (size_t)c * 16u);
    }
    cp_commit();
}
__device__ __forceinline__ uint32_t pipe_acquire(Pipe& p) {
    cp_wait2();
    __syncthreads();
    pipe_issue(p, p.u + 3);
    uint32_t s = p.swaddr + (uint32_t)(p.u & 3) * 8192u;
    p.u++;
    return s;
}

// ---------------- MMA tile: 3-term split, one 16-k panel ----------------
template<int NT>
__device__ __forceinline__ void mma_tile(float (*acc)[4], const uint32_t* ah, const uint32_t* al,
                                         uint32_t stage, int lane) {
    const int i = lane & 7, m = lane >> 3;
    const int row = ((m & 1) << 3) + i;
    const uint32_t rowoff = (uint32_t)row * (2 * NT);
    const int gsel = m >> 1;
#pragma unroll
    for (int j = 0; j < NT / 16; j++) {
        uint32_t ga = stage + rowoff + (uint32_t)((((2 * j + gsel) ^ i)) << 4);
        uint32_t bh[4]; ldsm4t(bh, ga);
        hmma(acc[2 * j],     ah, bh[0], bh[1]);
        hmma(acc[2 * j + 1], ah, bh[2], bh[3]);
        hmma(acc[2 * j],     al, bh[0], bh[1]);
        hmma(acc[2 * j + 1], al, bh[2], bh[3]);
        uint32_t bl[4]; ldsm4t(bl, ga + NT * 32);
        hmma(acc[2 * j],     ah, bl[0], bl[1]);
        hmma(acc[2 * j + 1], ah, bl[2], bl[3]);
    }
}

__device__ __forceinline__ void zero_acc(float (*acc)[4], int nt) {
#pragma unroll
    for (int j = 0; j < 16; j++)
        if (j < nt) { acc[j][0] = 0.f; acc[j][1] = 0.f; acc[j][2] = 0.f; acc[j][3] = 0.f; }
}

__device__ __forceinline__ void epi_relu128(const float (*acc)[4], const float* __restrict__ bias,
                                            uint32_t (*Ahi)[4], uint32_t (*Alo)[4], int q) {
#pragma unroll
    for (int t = 0; t < 8; t++) {
        float2 b0 = *(const float2*)(bias + 16 * t + 2 * q);
        float2 b1 = *(const float2*)(bias + 16 * t + 8 + 2 * q);
        float v00 = fmaxf(acc[2 * t][0] + b0.x, 0.f), v01 = fmaxf(acc[2 * t][1] + b0.y, 0.f);
        float v10 = fmaxf(acc[2 * t][2] + b0.x, 0.f), v11 = fmaxf(acc[2 * t][3] + b0.y, 0.f);
        float v20 = fmaxf(acc[2 * t + 1][0] + b1.x, 0.f), v21 = fmaxf(acc[2 * t + 1][1] + b1.y, 0.f);
        float v30 = fmaxf(acc[2 * t + 1][2] + b1.x, 0.f), v31 = fmaxf(acc[2 * t + 1][3] + b1.y, 0.f);
        split2(v00, v01, Ahi[t][0], Alo[t][0]);
        split2(v10, v11, Ahi[t][1], Alo[t][1]);
        split2(v20, v21, Ahi[t][2], Alo[t][2]);
        split2(v30, v31, Ahi[t][3], Alo[t][3]);
    }
}

__device__ __forceinline__ void ln_stats(const float (*acc)[4], const float* __restrict__ bias, int q,
                                         float (*vv)[4], float& muA, float& rsA, float& muB, float& rsB) {
    float sA = 0.f, sA2 = 0.f, sB = 0.f, sB2 = 0.f;
#pragma unroll
    for (int j = 0; j < 8; j++) {
        float2 b = *(const float2*)(bias + 8 * j + 2 * q);
        float v0 = acc[j][0] + b.x, v1 = acc[j][1] + b.y;
        float v2 = acc[j][2] + b.x, v3 = acc[j][3] + b.y;
        vv[j][0] = v0; vv[j][1] = v1; vv[j][2] = v2; vv[j][3] = v3;
        sA += v0 + v1; sA2 += v0 * v0 + v1 * v1;
        sB += v2 + v3; sB2 += v2 * v2 + v3 * v3;
    }
#pragma unroll
    for (int o = 1; o < 4; o <<= 1) {
        sA  += __shfl_xor_sync(0xffffffffu, sA, o);
        sA2 += __shfl_xor_sync(0xffffffffu, sA2, o);
        sB  += __shfl_xor_sync(0xffffffffu, sB, o);
        sB2 += __shfl_xor_sync(0xffffffffu, sB2, o);
    }
    muA = sA * (1.f / 64.f);
    rsA = rsqrtf(fmaxf(sA2 * (1.f / 64.f) - muA * muA, 0.f) + 1e-5f);
    muB = sB * (1.f / 64.f);
    rsB = rsqrtf(fmaxf(sB2 * (1.f / 64.f) - muB * muB, 0.f) + 1e-5f);
}

// ---------------------------------------------------------------------------
// prep kernel
// ---------------------------------------------------------------------------
__global__ void prep_kernel(const float* ew1, const float* ewh, const float* ew2,
                            const float* aw1, const float* awh, const float* aw2,
                            const float* nw1, const float* nwh, const float* nw2)
{
    const int N[12]  = {128,128,128,64,  128,128,128,64,  128,128,128,64};
    const uint32_t BASE[12] = {0,106496,172032,237568, 270336,376832,442368,507904,
                               540672,614400,679936,745472};
    const int CNT[12] = {26624,16384,16384,8192, 26624,16384,16384,8192, 18432,16384,16384,8192};
    const float* SRC[12] = {ew1, ewh, ewh + 16384, ew2, aw1, awh, awh + 16384, aw2,
                            nw1, nwh, nwh + 16384, nw2};

    int idx = blockIdx.x * blockDim.x + threadIdx.x;
    if (idx >= 194560) return;
    int t = 0, accu = 0;
    while (idx >= accu + CNT[t]) { accu += CNT[t]; t++; }
    int loc = idx - accu;
    int n = loc % N[t], k = loc / N[t];
    float v = SRC[t][(size_t)k * N[t] + n];
    __nv_bfloat16 h = __float2bfloat16(v);
    __nv_bfloat16 l = __float2bfloat16(v - __bfloat162float(h));
    uint32_t pb = (uint32_t)N[t] * 32u;
    uint32_t off = BASE[t] + (uint32_t)(k >> 4) * (pb * 2u)
                 + (uint32_t)(k & 15) * (uint32_t)(2 * N[t])
                 + (uint32_t)((((n >> 3) ^ (k & 7))) << 4) + (uint32_t)(n & 7) * 2u;
    *(__nv_bfloat16*)(g_wimg + off) = h;
    *(__nv_bfloat16*)(g_wimg + off + pb) = l;
}

// ---------------------------------------------------------------------------
// edge kernel: 128 threads, 64 edges/CTA, 2 CTAs/SM
// ---------------------------------------------------------------------------
__device__ __forceinline__ const float* eptr(int c, int row,
    const float* __restrict__ x, const float* __restrict__ ea, const float* __restrict__ u,
    const int* srcs, const int* tgts, const int* ebs, int e0) {
    if (c < 64)  return x  + (size_t)srcs[row] * 64 + c;
    if (c < 128) return x  + (size_t)tgts[row] * 64 + (c - 64);
    if (c < 192) return ea + (size_t)(e0 + row) * 64 + (c - 128);
    return u + (size_t)ebs[row] * 16 + (c - 192);
}

__global__ void __launch_bounds__(BLK, 2) edge_kernel(
    const float* __restrict__ x, const float* __restrict__ eattr,
    const float* __restrict__ u, const int* __restrict__ ei, const int* __restrict__ batch,
    const float* __restrict__ eb1, const float* __restrict__ ebh, const float* __restrict__ eb2,
    const float* __restrict__ eg,  const float* __restrict__ ebt,
    const float* __restrict__ ab1, const float* __restrict__ abh, const float* __restrict__ ab2,
    const float* __restrict__ ag,  const float* __restrict__ abt)
{
    __shared__ __align__(128) unsigned char sW[4 * 8192];
    __shared__ uint32_t sSrc[EDGE_UNITS];
    __shared__ uint16_t sChk[EDGE_UNITS];
    __shared__ int sIdx[3 * 64];

    const int tid = threadIdx.x;
    const int lane = tid & 31, warp = tid >> 5;
    const int q = lane & 3, rloc = lane >> 2;
    const int rA = warp * 16 + rloc, rB = rA + 8;
    const int e0 = blockIdx.x * 64;

    int* srcs = sIdx; int* tgts = sIdx + 64; int* ebs = sIdx + 128;
    if (tid < 64) {
        int s = ei[e0 + tid];
        int t = ei[N_EDGES + e0 + tid];
        srcs[tid] = s; tgts[tid] = t; ebs[tid] = batch[s];
    }
    if (tid == 0) {
        const int LU[8]  = {13, 8, 8, 8, 13, 8, 8, 8};
        const int LPB[8] = {4096, 4096, 4096, 2048, 4096, 4096, 4096, 2048};
        uint32_t off = 0; int uu = 0;
        for (int l = 0; l < 8; l++)
            for (int t = 0; t < LU[l]; t++) {
                sSrc[uu] = off; sChk[uu] = (uint16_t)((2 * LPB[l]) >> 4);
                off += 2 * LPB[l]; uu++;
            }
    }
    __syncthreads();

    Pipe p; p.swaddr = smem_u32(sW); p.srcOff = sSrc; p.chunks = sChk;
    p.base = g_wimg; p.nU = EDGE_UNITS; p.u = 0; p.tid = tid;
    pipe_issue(p, 0); pipe_issue(p, 1); pipe_issue(p, 2);

    float acc[16][4];
    uint32_t Ahi[8][4], Alo[8][4];
    float eo[8][4];

    const float* B1[2] = {eb1, ab1};
    const float* BH[2] = {ebh, abh};
    const float* B2[2] = {eb2, ab2};

    for (int mlp = 0; mlp < 2; mlp++) {
        zero_acc(acc, 16);
        for (int t = 0; t < 13; t++) {
            uint32_t ah4[4], al4[4];
            int c0 = 16 * t + 2 * q;
            float2 f0 = *(const float2*)eptr(c0,     rA, x, eattr, u, srcs, tgts, ebs, e0);
            float2 f1 = *(const float2*)eptr(c0,     rB, x, eattr, u, srcs, tgts, ebs, e0);
            float2 f2 = *(const float2*)eptr(c0 + 8, rA, x, eattr, u, srcs, tgts, ebs, e0);
            float2 f3 = *(const float2*)eptr(c0 + 8, rB, x, eattr, u, srcs, tgts, ebs, e0);
            split2(f0.x, f0.y, ah4[0], al4[0]);
            split2(f1.x, f1.y, ah4[1], al4[1]);
            split2(f2.x, f2.y, ah4[2], al4[2]);
            split2(f3.x, f3.y, ah4[3], al4[3]);
            uint32_t st = pipe_acquire(p);
            mma_tile<128>(acc, ah4, al4, st, lane);
        }
        epi_relu128(acc, B1[mlp], Ahi, Alo, q);

        for (int hl = 0; hl < 2; hl++) {
            zero_acc(acc, 16);
            for (int t = 0; t < 8; t++) {
                uint32_t st = pipe_acquire(p);
                mma_tile<128>(acc, Ahi[t], Alo[t], st, lane);
            }
            epi_relu128(acc, BH[mlp] + hl * 128, Ahi, Alo, q);
        }

        zero_acc(acc, 8);
        for (int t = 0; t < 8; t++) {
            uint32_t st = pipe_acquire(p);
            mma_tile<64>(acc, Ahi[t], Alo[t], st, lane);
        }
        float vv[8][4], muA, rsA, muB, rsB;
        ln_stats(acc, B2[mlp], q, vv, muA, rsA, muB, rsB);
        if (mlp == 0) {
#pragma unroll
            for (int j = 0; j < 8; j++) {
                int c = 8 * j + 2 * q;
                float2 gm = *(const float2*)(eg + c);
                float2 bt = *(const float2*)(ebt + c);
                eo[j][0] = (vv[j][0] - muA) * rsA * gm.x + bt.x;
                eo[j][1] = (vv[j][1] - muA) * rsA * gm.y + bt.y;
                eo[j][2] = (vv[j][2] - muB) * rsB * gm.x + bt.x;
                eo[j][3] = (vv[j][3] - muB) * rsB * gm.y + bt.y;
            }
        } else {
            float* rowP_A = g_agg + (size_t)tgts[rA] * 64;
            float* rowP_B = g_agg + (size_t)tgts[rB] * 64;
#pragma unroll
            for (int j = 0; j < 8; j++) {
                int c = 8 * j + 2 * q;
                float2 gm = *(const float2*)(ag + c);
                float2 bt = *(const float2*)(abt + c);
                float a0 = (vv[j][0] - muA) * rsA * gm.x + bt.x;
                float a1 = (vv[j][1] - muA) * rsA * gm.y + bt.y;
                float a2 = (vv[j][2] - muB) * rsB * gm.x + bt.x;
                float a3 = (vv[j][3] - muB) * rsB * gm.y + bt.y;
                atomicAdd(rowP_A + c,     eo[j][0] / (1.f + expf(-a0)));
                atomicAdd(rowP_A + c + 1, eo[j][1] / (1.f + expf(-a1)));
                atomicAdd(rowP_B + c,     eo[j][2] / (1.f + expf(-a2)));
                atomicAdd(rowP_B + c + 1, eo[j][3] / (1.f + expf(-a3)));
            }
        }
    }
}

// ---------------------------------------------------------------------------
// node kernel: 128 threads, 64 nodes/CTA
// ---------------------------------------------------------------------------
__device__ __forceinline__ const float* nptr(int c, int n, int bt,
    const float* __restrict__ x, const float* __restrict__ u) {
    if (c < 64)  return x + (size_t)n * 64 + c;
    if (c < 128) return g_agg + (size_t)n * 64 + (c - 64);
    return u + (size_t)bt * 16 + (c - 128);
}

__global__ void __launch_bounds__(BLK, 2) node_kernel(
    const float* __restrict__ x, const float* __restrict__ u, const int* __restrict__ batch,
    const float* __restrict__ nb1, const float* __restrict__ nbh, const float* __restrict__ nb2,
    const float* __restrict__ ng,  const float* __restrict__ nbt,
    float* __restrict__ out)
{
    __shared__ __align__(128) unsigned char sW[4 * 8192];
    __shared__ uint32_t sSrc[NODE_UNITS];
    __shared__ uint16_t sChk[NODE_UNITS];
    __shared__ int sBt[64];

    const int tid = threadIdx.x;
    const int lane = tid & 31, warp = tid >> 5;
    const int q = lane & 3, rloc = lane >> 2;
    const int rA = warp * 16 + rloc, rB = rA + 8;
    const int n0 = blockIdx.x * 64;

    if (tid < 64) {
        int n = n0 + tid;
        sBt[tid] = (n < N_NODES) ? batch[n] : 0;
    }
    if (tid == 0) {
        const int LU[4]  = {9, 8, 8, 8};
        const int LPB[4] = {4096, 4096, 4096, 2048};
        uint32_t off = 0; int uu = 0;
        for (int l = 0; l < 4; l++)
            for (int t = 0; t < LU[l]; t++) {
                sSrc[uu] = off; sChk[uu] = (uint16_t)((2 * LPB[l]) >> 4);
                off += 2 * LPB[l]; uu++;
            }
    }
    __syncthreads();

    Pipe p; p.swaddr = smem_u32(sW); p.srcOff = sSrc; p.chunks = sChk;
    p.base = g_wimg + NODE_BASE; p.nU = NODE_UNITS; p.u = 0; p.tid = tid;
    pipe_issue(p, 0); pipe_issue(p, 1); pipe_issue(p, 2);

    const int nA = (n0 + rA < N_NODES) ? n0 + rA : N_NODES - 1;
    const int nB = (n0 + rB < N_NODES) ? n0 + rB : N_NODES - 1;
    const int btA = sBt[rA], btB = sBt[rB];

    float acc[16][4];
    uint32_t Ahi[8][4], Alo[8][4];

    zero_acc(acc, 16);
    for (int t = 0; t < 9; t++) {
        uint32_t ah4[4], al4[4];
        int c0 = 16 * t + 2 * q;
        float2 f0 = *(const float2*)nptr(c0,     nA, btA, x, u);
        float2 f1 = *(const float2*)nptr(c0,     nB, btB, x, u);
        float2 f2 = *(const float2*)nptr(c0 + 8, nA, btA, x, u);
        float2 f3 = *(const float2*)nptr(c0 + 8, nB, btB, x, u);
        split2(f0.x, f0.y, ah4[0], al4[0]);
        split2(f1.x, f1.y, ah4[1], al4[1]);
        split2(f2.x, f2.y, ah4[2], al4[2]);
        split2(f3.x, f3.y, ah4[3], al4[3]);
        uint32_t st = pipe_acquire(p);
        mma_tile<128>(acc, ah4, al4, st, lane);
    }
    epi_relu128(acc, nb1, Ahi, Alo, q);

    for (int hl = 0; hl < 2; hl++) {
        zero_acc(acc, 16);
        for (int t = 0; t < 8; t++) {
            uint32_t st = pipe_acquire(p);
            mma_tile<128>(acc, Ahi[t], Alo[t], st, lane);
        }
        epi_relu128(acc, nbh + hl * 128, Ahi, Alo, q);
    }

    zero_acc(acc, 8);
    for (int t = 0; t < 8; t++) {
        uint32_t st = pipe_acquire(p);
        mma_tile<64>(acc, Ahi[t], Alo[t], st, lane);
    }
    float vv[8][4], muA, rsA, muB, rsB;
    ln_stats(acc, nb2, q, vv, muA, rsA, muB, rsB);

    const bool vA = (n0 + rA < N_NODES), vB = (n0 + rB < N_NODES);
#pragma unroll
    for (int j = 0; j < 8; j++) {
        int c = 8 * j + 2 * q;
        float2 gm = *(const float2*)(ng + c);
        float2 bt = *(const float2*)(nbt + c);
        if (vA) {
            float2 o; o.x = (vv[j][0] - muA) * rsA * gm.x + bt.x;
            o.y = (vv[j][1] - muA) * rsA * gm.y + bt.y;
            *(float2*)(out + (size_t)(n0 + rA) * 64 + c) = o;
        }
        if (vB) {
            float2 o; o.x = (vv[j][2] - muB) * rsB * gm.x + bt.x;
            o.y = (vv[j][3] - muB) * rsB * gm.y + bt.y;
            *(float2*)(out + (size_t)(n0 + rB) * 64 + c) = o;
        }
    }
}

// ---------------------------------------------------------------------------
extern "C" void kernel_launch(void* const* d_in, const int* in_sizes, int n_in,
                              void* d_out, int out_size)
{
    const float* x     = (const float*)d_in[0];
    const float* eattr = (const float*)d_in[1];
    const float* u     = (const float*)d_in[2];
    const int*   ei    = (const int*)d_in[3];
    const int*   batch = (const int*)d_in[4];
    const float* ew1 = (const float*)d_in[5],  *eb1 = (const float*)d_in[6];
    const float* ewh = (const float*)d_in[7],  *ebh = (const float*)d_in[8];
    const float* ew2 = (const float*)d_in[9],  *eb2 = (const float*)d_in[10];
    const float* eg  = (const float*)d_in[11], *ebt = (const float*)d_in[12];
    const float* aw1 = (const float*)d_in[13], *ab1 = (const float*)d_in[14];
    const float* awh = (const float*)d_in[15], *abh = (const float*)d_in[16];
    const float* aw2 = (const float*)d_in[17], *ab2 = (const float*)d_in[18];
    const float* ag  = (const float*)d_in[19], *abt = (const float*)d_in[20];
    const float* nw1 = (const float*)d_in[21], *nb1 = (const float*)d_in[22];
    const float* nwh = (const float*)d_in[23], *nbh = (const float*)d_in[24];
    const float* nw2 = (const float*)d_in[25], *nb2 = (const float*)d_in[26];
    const float* ng  = (const float*)d_in[27], *nbt = (const float*)d_in[28];
    float* out = (float*)d_out;
    (void)in_sizes; (void)n_in; (void)out_size;

    void* aggp = nullptr;
    cudaGetSymbolAddress(&aggp, g_agg);
    cudaMemsetAsync(aggp, 0, sizeof(float) * (size_t)N_NODES * 64, 0);

    prep_kernel<<<(194560 + 255) / 256, 256>>>(ew1, ewh, ew2, aw1, awh, aw2, nw1, nwh, nw2);

    edge_kernel<<<N_EDGES / 64, BLK>>>(
        x, eattr, u, ei, batch,
        eb1, ebh, eb2, eg, ebt,
        ab1, abh, ab2, ag, abt);

    node_kernel<<<(N_NODES + 63) / 64, BLK>>>(
        x, u, batch, nb1, nbh, nb2, ng, nbt, out);
}

// round 6
// speedup vs baseline: 3.5874x; 1.1612x over previous
#include <cuda_runtime.h>
#include <cuda_bf16.h>
#include <cstdint>
#include <math.h>

#define N_NODES 50000
#define N_EDGES 400000

// ---------------- device scratch ----------------
__device__ float g_agg[(size_t)N_NODES * 64];
__device__ __align__(128) unsigned char g_wimg[778240];

#define EDGE_UNITS 74
#define NODE_UNITS 33
#define NODE_BASE  540672u
#define BLK 128

// ---------------- low-level helpers ----------------
__device__ __forceinline__ uint32_t smem_u32(const void* p) {
    uint32_t a;
    asm("{ .reg .u64 t; cvta.to.shared.u64 t, %1; cvt.u32.u64 %0, t; }" : "=r"(a) : "l"(p));
    return a;
}
#define MBAR_INIT(a, c) \
    asm volatile("mbarrier.init.shared.b64 [%0], %1;" :: "r"(a), "r"(c) : "memory")
#define MBAR_EXPECT_TX(a, b) \
    asm volatile("mbarrier.arrive.expect_tx.shared.b64 _, [%0], %1;" :: "r"(a), "r"(b) : "memory")

__device__ __forceinline__ void mbar_wait(uint32_t mbar, uint32_t parity) {
    uint32_t done;
    asm volatile(
        "{\n\t.reg .pred p;\n\t"
        "mbarrier.try_wait.parity.acquire.cta.shared::cta.b64 p, [%1], %2;\n\t"
        "selp.b32 %0, 1, 0, p;\n\t}"
        : "=r"(done) : "r"(mbar), "r"(parity) : "memory");
    if (!done) {
        asm volatile(
            "{\n\t.reg .pred P1;\n\t"
            "WL_%=:\n\t"
            "mbarrier.try_wait.parity.acquire.cta.shared::cta.b64 P1, [%0], %1, 0x989680;\n\t"
            "@P1 bra.uni WD_%=;\n\t"
            "bra.uni WL_%=;\n\t"
            "WD_%=:\n\t}"
            :: "r"(mbar), "r"(parity) : "memory");
    }
}
__device__ __forceinline__ void bulk_cp(uint32_t dst, const void* src, uint32_t bytes, uint32_t bar) {
    asm volatile(
        "cp.async.bulk.shared::cluster.global.mbarrier::complete_tx::bytes [%0], [%1], %2, [%3];"
        :: "r"(dst), "l"(src), "r"(bytes), "r"(bar) : "memory");
}

__device__ __forceinline__ void ldsm4t(uint32_t* r, uint32_t addr) {
    asm volatile("ldmatrix.sync.aligned.m8n8.x4.trans.shared.b16 {%0,%1,%2,%3}, [%4];"
        : "=r"(r[0]), "=r"(r[1]), "=r"(r[2]), "=r"(r[3]) : "r"(addr));
}
__device__ __forceinline__ void hmma(float* c, const uint32_t* a, uint32_t b0, uint32_t b1) {
    asm volatile("mma.sync.aligned.m16n8k16.row.col.f32.bf16.bf16.f32 "
        "{%0,%1,%2,%3}, {%4,%5,%6,%7}, {%8,%9}, {%0,%1,%2,%3};"
        : "+f"(c[0]), "+f"(c[1]), "+f"(c[2]), "+f"(c[3])
        : "r"(a[0]), "r"(a[1]), "r"(a[2]), "r"(a[3]), "r"(b0), "r"(b1));
}
__device__ __forceinline__ void split2(float a, float b, uint32_t& h, uint32_t& l) {
    __nv_bfloat162 hb = __floats2bfloat162_rn(a, b);
    float ra = a - __bfloat162float(__low2bfloat16(hb));
    float rb = b - __bfloat162float(__high2bfloat16(hb));
    __nv_bfloat162 lb = __floats2bfloat162_rn(ra, rb);
    h = *reinterpret_cast<uint32_t*>(&hb);
    l = *reinterpret_cast<uint32_t*>(&lb);
}

// ---------------- weight-stream pipeline (bulk DMA, 4-stage ring) ----------------
struct Pipe {
    uint32_t swaddr;            // 4 x 8192 stage base
    uint32_t mbar;              // 4 mbarriers, 8B apart
    const uint32_t* srcOff;     // per-unit byte offset
    const uint16_t* byt;        // per-unit byte count (<=8192)
    const unsigned char* base;
    int nU;
    int u;
    bool leader;
};
__device__ __forceinline__ void pipe_issue(Pipe& p, int v) {
    if (p.leader && v < p.nU) {
        uint32_t s = (uint32_t)(v & 3);
        uint32_t bar = p.mbar + s * 8u;
        uint32_t nb = p.byt[v];
        MBAR_EXPECT_TX(bar, nb);
        bulk_cp(p.swaddr + s * 8192u, p.base + p.srcOff[v], nb, bar);
    }
}
__device__ __forceinline__ uint32_t pipe_acquire(Pipe& p) {
    int u = p.u;
    __syncthreads();                       // all warps done with unit u-1 (stage (u+3)&3 free)
    pipe_issue(p, u + 3);
    mbar_wait(p.mbar + (uint32_t)(u & 3) * 8u, (uint32_t)((u >> 2) & 1));
    p.u = u + 1;
    return p.swaddr + (uint32_t)(u & 3) * 8192u;
}

// ---------------- MMA tile: 3-term split, one 16-k panel ----------------
template<int NT>
__device__ __forceinline__ void mma_tile(float (*acc)[4], const uint32_t* ah, const uint32_t* al,
                                         uint32_t stage, int lane) {
    const int i = lane & 7, m = lane >> 3;
    const int row = ((m & 1) << 3) + i;
    const uint32_t rowoff = (uint32_t)row * (2 * NT);
    const int gsel = m >> 1;
#pragma unroll
    for (int j = 0; j < NT / 16; j++) {
        uint32_t ga = stage + rowoff + (uint32_t)((((2 * j + gsel) ^ i)) << 4);
        uint32_t bh[4]; ldsm4t(bh, ga);
        hmma(acc[2 * j],     ah, bh[0], bh[1]);
        hmma(acc[2 * j + 1], ah, bh[2], bh[3]);
        hmma(acc[2 * j],     al, bh[0], bh[1]);
        hmma(acc[2 * j + 1], al, bh[2], bh[3]);
        uint32_t bl[4]; ldsm4t(bl, ga + NT * 32);
        hmma(acc[2 * j],     ah, bl[0], bl[1]);
        hmma(acc[2 * j + 1], ah, bl[2], bl[3]);
    }
}

__device__ __forceinline__ void zero_acc(float (*acc)[4], int nt) {
#pragma unroll
    for (int j = 0; j < 16; j++)
        if (j < nt) { acc[j][0] = 0.f; acc[j][1] = 0.f; acc[j][2] = 0.f; acc[j][3] = 0.f; }
}

__device__ __forceinline__ void epi_relu128(const float (*acc)[4], const float* __restrict__ bias,
                                            uint32_t (*Ahi)[4], uint32_t (*Alo)[4], int q) {
#pragma unroll
    for (int t = 0; t < 8; t++) {
        float2 b0 = *(const float2*)(bias + 16 * t + 2 * q);
        float2 b1 = *(const float2*)(bias + 16 * t + 8 + 2 * q);
        float v00 = fmaxf(acc[2 * t][0] + b0.x, 0.f), v01 = fmaxf(acc[2 * t][1] + b0.y, 0.f);
        float v10 = fmaxf(acc[2 * t][2] + b0.x, 0.f), v11 = fmaxf(acc[2 * t][3] + b0.y, 0.f);
        float v20 = fmaxf(acc[2 * t + 1][0] + b1.x, 0.f), v21 = fmaxf(acc[2 * t + 1][1] + b1.y, 0.f);
        float v30 = fmaxf(acc[2 * t + 1][2] + b1.x, 0.f), v31 = fmaxf(acc[2 * t + 1][3] + b1.y, 0.f);
        split2(v00, v01, Ahi[t][0], Alo[t][0]);
        split2(v10, v11, Ahi[t][1], Alo[t][1]);
        split2(v20, v21, Ahi[t][2], Alo[t][2]);
        split2(v30, v31, Ahi[t][3], Alo[t][3]);
    }
}

__device__ __forceinline__ void ln_stats(const float (*acc)[4], const float* __restrict__ bias, int q,
                                         float (*vv)[4], float& muA, float& rsA, float& muB, float& rsB) {
    float sA = 0.f, sA2 = 0.f, sB = 0.f, sB2 = 0.f;
#pragma unroll
    for (int j = 0; j < 8; j++) {
        float2 b = *(const float2*)(bias + 8 * j + 2 * q);
        float v0 = acc[j][0] + b.x, v1 = acc[j][1] + b.y;
        float v2 = acc[j][2] + b.x, v3 = acc[j][3] + b.y;
        vv[j][0] = v0; vv[j][1] = v1; vv[j][2] = v2; vv[j][3] = v3;
        sA += v0 + v1; sA2 += v0 * v0 + v1 * v1;
        sB += v2 + v3; sB2 += v2 * v2 + v3 * v3;
    }
#pragma unroll
    for (int o = 1; o < 4; o <<= 1) {
        sA  += __shfl_xor_sync(0xffffffffu, sA, o);
        sA2 += __shfl_xor_sync(0xffffffffu, sA2, o);
        sB  += __shfl_xor_sync(0xffffffffu, sB, o);
        sB2 += __shfl_xor_sync(0xffffffffu, sB2, o);
    }
    muA = sA * (1.f / 64.f);
    rsA = rsqrtf(fmaxf(sA2 * (1.f / 64.f) - muA * muA, 0.f) + 1e-5f);
    muB = sB * (1.f / 64.f);
    rsB = rsqrtf(fmaxf(sB2 * (1.f / 64.f) - muB * muB, 0.f) + 1e-5f);
}

// ---------------------------------------------------------------------------
// prep kernel
// ---------------------------------------------------------------------------
__global__ void prep_kernel(const float* ew1, const float* ewh, const float* ew2,
                            const float* aw1, const float* awh, const float* aw2,
                            const float* nw1, const float* nwh, const float* nw2)
{
    const int N[12]  = {128,128,128,64,  128,128,128,64,  128,128,128,64};
    const uint32_t BASE[12] = {0,106496,172032,237568, 270336,376832,442368,507904,
                               540672,614400,679936,745472};
    const int CNT[12] = {26624,16384,16384,8192, 26624,16384,16384,8192, 18432,16384,16384,8192};
    const float* SRC[12] = {ew1, ewh, ewh + 16384, ew2, aw1, awh, awh + 16384, aw2,
                            nw1, nwh, nwh + 16384, nw2};

    int idx = blockIdx.x * blockDim.x + threadIdx.x;
    if (idx >= 194560) return;
    int t = 0, accu = 0;
    while (idx >= accu + CNT[t]) { accu += CNT[t]; t++; }
    int loc = idx - accu;
    int n = loc % N[t], k = loc / N[t];
    float v = SRC[t][(size_t)k * N[t] + n];
    __nv_bfloat16 h = __float2bfloat16(v);
    __nv_bfloat16 l = __float2bfloat16(v - __bfloat162float(h));
    uint32_t pb = (uint32_t)N[t] * 32u;
    uint32_t off = BASE[t] + (uint32_t)(k >> 4) * (pb * 2u)
                 + (uint32_t)(k & 15) * (uint32_t)(2 * N[t])
                 + (uint32_t)((((n >> 3) ^ (k & 7))) << 4) + (uint32_t)(n & 7) * 2u;
    *(__nv_bfloat16*)(g_wimg + off) = h;
    *(__nv_bfloat16*)(g_wimg + off + pb) = l;
}

// ---------------------------------------------------------------------------
// edge kernel: 128 threads, 64 edges/CTA, 2 CTAs/SM
// ---------------------------------------------------------------------------
__device__ __forceinline__ const float* eptr(int c, int row,
    const float* __restrict__ x, const float* __restrict__ ea, const float* __restrict__ u,
    const int* srcs, const int* tgts, const int* ebs, int e0) {
    if (c < 64)  return x  + (size_t)srcs[row] * 64 + c;
    if (c < 128) return x  + (size_t)tgts[row] * 64 + (c - 64);
    if (c < 192) return ea + (size_t)(e0 + row) * 64 + (c - 128);
    return u + (size_t)ebs[row] * 16 + (c - 192);
}

__global__ void __launch_bounds__(BLK, 2) edge_kernel(
    const float* __restrict__ x, const float* __restrict__ eattr,
    const float* __restrict__ u, const int* __restrict__ ei, const int* __restrict__ batch,
    const float* __restrict__ eb1, const float* __restrict__ ebh, const float* __restrict__ eb2,
    const float* __restrict__ eg,  const float* __restrict__ ebt,
    const float* __restrict__ ab1, const float* __restrict__ abh, const float* __restrict__ ab2,
    const float* __restrict__ ag,  const float* __restrict__ abt)
{
    __shared__ __align__(128) unsigned char sW[4 * 8192];
    __shared__ __align__(8) unsigned long long sBar[4];
    __shared__ uint32_t sSrc[EDGE_UNITS];
    __shared__ uint16_t sByt[EDGE_UNITS];
    __shared__ int sIdx[3 * 64];

    const int tid = threadIdx.x;
    const int lane = tid & 31, warp = tid >> 5;
    const int q = lane & 3, rloc = lane >> 2;
    const int rA = warp * 16 + rloc, rB = rA + 8;
    const int e0 = blockIdx.x * 64;

    int* srcs = sIdx; int* tgts = sIdx + 64; int* ebs = sIdx + 128;
    if (tid < 64) {
        int s = ei[e0 + tid];
        int t = ei[N_EDGES + e0 + tid];
        srcs[tid] = s; tgts[tid] = t; ebs[tid] = batch[s];
    }
    uint32_t mb = smem_u32(sBar);
    if (tid == 0) {
        for (int s = 0; s < 4; s++) MBAR_INIT(mb + s * 8u, 1);
        const int LU[8]  = {13, 8, 8, 8, 13, 8, 8, 8};
        const int LPB[8] = {4096, 4096, 4096, 2048, 4096, 4096, 4096, 2048};
        uint32_t off = 0; int uu = 0;
        for (int l = 0; l < 8; l++)
            for (int t = 0; t < LU[l]; t++) {
                sSrc[uu] = off; sByt[uu] = (uint16_t)(2 * LPB[l]);
                off += 2 * LPB[l]; uu++;
            }
    }
    __syncthreads();

    Pipe p; p.swaddr = smem_u32(sW); p.mbar = mb; p.srcOff = sSrc; p.byt = sByt;
    p.base = g_wimg; p.nU = EDGE_UNITS; p.u = 0; p.leader = (tid == 0);
    pipe_issue(p, 0); pipe_issue(p, 1); pipe_issue(p, 2);

    float acc[16][4];
    uint32_t Ahi[8][4], Alo[8][4];
    float eo[8][4];

    const float* B1[2] = {eb1, ab1};
    const float* BH[2] = {ebh, abh};
    const float* B2[2] = {eb2, ab2};

    for (int mlp = 0; mlp < 2; mlp++) {
        zero_acc(acc, 16);
        for (int t = 0; t < 13; t++) {
            uint32_t ah4[4], al4[4];
            int c0 = 16 * t + 2 * q;
            float2 f0 = *(const float2*)eptr(c0,     rA, x, eattr, u, srcs, tgts, ebs, e0);
            float2 f1 = *(const float2*)eptr(c0,     rB, x, eattr, u, srcs, tgts, ebs, e0);
            float2 f2 = *(const float2*)eptr(c0 + 8, rA, x, eattr, u, srcs, tgts, ebs, e0);
            float2 f3 = *(const float2*)eptr(c0 + 8, rB, x, eattr, u, srcs, tgts, ebs, e0);
            split2(f0.x, f0.y, ah4[0], al4[0]);
            split2(f1.x, f1.y, ah4[1], al4[1]);
            split2(f2.x, f2.y, ah4[2], al4[2]);
            split2(f3.x, f3.y, ah4[3], al4[3]);
            uint32_t st = pipe_acquire(p);
            mma_tile<128>(acc, ah4, al4, st, lane);
        }
        epi_relu128(acc, B1[mlp], Ahi, Alo, q);

        for (int hl = 0; hl < 2; hl++) {
            zero_acc(acc, 16);
            for (int t = 0; t < 8; t++) {
                uint32_t st = pipe_acquire(p);
                mma_tile<128>(acc, Ahi[t], Alo[t], st, lane);
            }
            epi_relu128(acc, BH[mlp] + hl * 128, Ahi, Alo, q);
        }

        zero_acc(acc, 8);
        for (int t = 0; t < 8; t++) {
            uint32_t st = pipe_acquire(p);
            mma_tile<64>(acc, Ahi[t], Alo[t], st, lane);
        }
        float vv[8][4], muA, rsA, muB, rsB;
        ln_stats(acc, B2[mlp], q, vv, muA, rsA, muB, rsB);
        if (mlp == 0) {
#pragma unroll
            for (int j = 0; j < 8; j++) {
                int c = 8 * j + 2 * q;
                float2 gm = *(const float2*)(eg + c);
                float2 bt = *(const float2*)(ebt + c);
                eo[j][0] = (vv[j][0] - muA) * rsA * gm.x + bt.x;
                eo[j][1] = (vv[j][1] - muA) * rsA * gm.y + bt.y;
                eo[j][2] = (vv[j][2] - muB) * rsB * gm.x + bt.x;
                eo[j][3] = (vv[j][3] - muB) * rsB * gm.y + bt.y;
            }
        } else {
            float* rowP_A = g_agg + (size_t)tgts[rA] * 64;
            float* rowP_B = g_agg + (size_t)tgts[rB] * 64;
#pragma unroll
            for (int j = 0; j < 8; j++) {
                int c = 8 * j + 2 * q;
                float2 gm = *(const float2*)(ag + c);
                float2 bt = *(const float2*)(abt + c);
                float a0 = (vv[j][0] - muA) * rsA * gm.x + bt.x;
                float a1 = (vv[j][1] - muA) * rsA * gm.y + bt.y;
                float a2 = (vv[j][2] - muB) * rsB * gm.x + bt.x;
                float a3 = (vv[j][3] - muB) * rsB * gm.y + bt.y;
                atomicAdd(rowP_A + c,     eo[j][0] / (1.f + expf(-a0)));
                atomicAdd(rowP_A + c + 1, eo[j][1] / (1.f + expf(-a1)));
                atomicAdd(rowP_B + c,     eo[j][2] / (1.f + expf(-a2)));
                atomicAdd(rowP_B + c + 1, eo[j][3] / (1.f + expf(-a3)));
            }
        }
    }
}

// ---------------------------------------------------------------------------
// node kernel: 128 threads, 64 nodes/CTA
// ---------------------------------------------------------------------------
__device__ __forceinline__ const float* nptr(int c, int n, int bt,
    const float* __restrict__ x, const float* __restrict__ u) {
    if (c < 64)  return x + (size_t)n * 64 + c;
    if (c < 128) return g_agg + (size_t)n * 64 + (c - 64);
    return u + (size_t)bt * 16 + (c - 128);
}

__global__ void __launch_bounds__(BLK, 2) node_kernel(
    const float* __restrict__ x, const float* __restrict__ u, const int* __restrict__ batch,
    const float* __restrict__ nb1, const float* __restrict__ nbh, const float* __restrict__ nb2,
    const float* __restrict__ ng,  const float* __restrict__ nbt,
    float* __restrict__ out)
{
    __shared__ __align__(128) unsigned char sW[4 * 8192];
    __shared__ __align__(8) unsigned long long sBar[4];
    __shared__ uint32_t sSrc[NODE_UNITS];
    __shared__ uint16_t sByt[NODE_UNITS];
    __shared__ int sBt[64];

    const int tid = threadIdx.x;
    const int lane = tid & 31, warp = tid >> 5;
    const int q = lane & 3, rloc = lane >> 2;
    const int rA = warp * 16 + rloc, rB = rA + 8;
    const int n0 = blockIdx.x * 64;

    if (tid < 64) {
        int n = n0 + tid;
        sBt[tid] = (n < N_NODES) ? batch[n] : 0;
    }
    uint32_t mb = smem_u32(sBar);
    if (tid == 0) {
        for (int s = 0; s < 4; s++) MBAR_INIT(mb + s * 8u, 1);
        const int LU[4]  = {9, 8, 8, 8};
        const int LPB[4] = {4096, 4096, 4096, 2048};
        uint32_t off = 0; int uu = 0;
        for (int l = 0; l < 4; l++)
            for (int t = 0; t < LU[l]; t++) {
                sSrc[uu] = off; sByt[uu] = (uint16_t)(2 * LPB[l]);
                off += 2 * LPB[l]; uu++;
            }
    }
    __syncthreads();

    Pipe p; p.swaddr = smem_u32(sW); p.mbar = mb; p.srcOff = sSrc; p.byt = sByt;
    p.base = g_wimg + NODE_BASE; p.nU = NODE_UNITS; p.u = 0; p.leader = (tid == 0);
    pipe_issue(p, 0); pipe_issue(p, 1); pipe_issue(p, 2);

    const int nA = (n0 + rA < N_NODES) ? n0 + rA : N_NODES - 1;
    const int nB = (n0 + rB < N_NODES) ? n0 + rB : N_NODES - 1;
    const int btA = sBt[rA], btB = sBt[rB];

    float acc[16][4];
    uint32_t Ahi[8][4], Alo[8][4];

    zero_acc(acc, 16);
    for (int t = 0; t < 9; t++) {
        uint32_t ah4[4], al4[4];
        int c0 = 16 * t + 2 * q;
        float2 f0 = *(const float2*)nptr(c0,     nA, btA, x, u);
        float2 f1 = *(const float2*)nptr(c0,     nB, btB, x, u);
        float2 f2 = *(const float2*)nptr(c0 + 8, nA, btA, x, u);
        float2 f3 = *(const float2*)nptr(c0 + 8, nB, btB, x, u);
        split2(f0.x, f0.y, ah4[0], al4[0]);
        split2(f1.x, f1.y, ah4[1], al4[1]);
        split2(f2.x, f2.y, ah4[2], al4[2]);
        split2(f3.x, f3.y, ah4[3], al4[3]);
        uint32_t st = pipe_acquire(p);
        mma_tile<128>(acc, ah4, al4, st, lane);
    }
    epi_relu128(acc, nb1, Ahi, Alo, q);

    for (int hl = 0; hl < 2; hl++) {
        zero_acc(acc, 16);
        for (int t = 0; t < 8; t++) {
            uint32_t st = pipe_acquire(p);
            mma_tile<128>(acc, Ahi[t], Alo[t], st, lane);
        }
        epi_relu128(acc, nbh + hl * 128, Ahi, Alo, q);
    }

    zero_acc(acc, 8);
    for (int t = 0; t < 8; t++) {
        uint32_t st = pipe_acquire(p);
        mma_tile<64>(acc, Ahi[t], Alo[t], st, lane);
    }
    float vv[8][4], muA, rsA, muB, rsB;
    ln_stats(acc, nb2, q, vv, muA, rsA, muB, rsB);

    const bool vA = (n0 + rA < N_NODES), vB = (n0 + rB < N_NODES);
#pragma unroll
    for (int j = 0; j < 8; j++) {
        int c = 8 * j + 2 * q;
        float2 gm = *(const float2*)(ng + c);
        float2 bt = *(const float2*)(nbt + c);
        if (vA) {
            float2 o; o.x = (vv[j][0] - muA) * rsA * gm.x + bt.x;
            o.y = (vv[j][1] - muA) * rsA * gm.y + bt.y;
            *(float2*)(out + (size_t)(n0 + rA) * 64 + c) = o;
        }
        if (vB) {
            float2 o; o.x = (vv[j][2] - muB) * rsB * gm.x + bt.x;
            o.y = (vv[j][3] - muB) * rsB * gm.y + bt.y;
            *(float2*)(out + (size_t)(n0 + rB) * 64 + c) = o;
        }
    }
}

// ---------------------------------------------------------------------------
extern "C" void kernel_launch(void* const* d_in, const int* in_sizes, int n_in,
                              void* d_out, int out_size)
{
    const float* x     = (const float*)d_in[0];
    const float* eattr = (const float*)d_in[1];
    const float* u     = (const float*)d_in[2];
    const int*   ei    = (const int*)d_in[3];
    const int*   batch = (const int*)d_in[4];
    const float* ew1 = (const float*)d_in[5],  *eb1 = (const float*)d_in[6];
    const float* ewh = (const float*)d_in[7],  *ebh = (const float*)d_in[8];
    const float* ew2 = (const float*)d_in[9],  *eb2 = (const float*)d_in[10];
    const float* eg  = (const float*)d_in[11], *ebt = (const float*)d_in[12];
    const float* aw1 = (const float*)d_in[13], *ab1 = (const float*)d_in[14];
    const float* awh = (const float*)d_in[15], *abh = (const float*)d_in[16];
    const float* aw2 = (const float*)d_in[17], *ab2 = (const float*)d_in[18];
    const float* ag  = (const float*)d_in[19], *abt = (const float*)d_in[20];
    const float* nw1 = (const float*)d_in[21], *nb1 = (const float*)d_in[22];
    const float* nwh = (const float*)d_in[23], *nbh = (const float*)d_in[24];
    const float* nw2 = (const float*)d_in[25], *nb2 = (const float*)d_in[26];
    const float* ng  = (const float*)d_in[27], *nbt = (const float*)d_in[28];
    float* out = (float*)d_out;
    (void)in_sizes; (void)n_in; (void)out_size;

    void* aggp = nullptr;
    cudaGetSymbolAddress(&aggp, g_agg);
    cudaMemsetAsync(aggp, 0, sizeof(float) * (size_t)N_NODES * 64, 0);

    prep_kernel<<<(194560 + 255) / 256, 256>>>(ew1, ewh, ew2, aw1, awh, aw2, nw1, nwh, nw2);

    edge_kernel<<<N_EDGES / 64, BLK>>>(
        x, eattr, u, ei, batch,
        eb1, ebh, eb2, eg, ebt,
        ab1, abh, ab2, ag, abt);

    node_kernel<<<(N_NODES + 63) / 64, BLK>>>(
        x, u, batch, nb1, nbh, nb2, ng, nbt, out);
}